// round 11
// baseline (speedup 1.0000x reference)
#include <cuda_runtime.h>
#include <cooperative_groups.h>
#include <math.h>

namespace cg = cooperative_groups;

// Problem constants
#define SEQ   1024
#define TB    64
#define EMBD  512
#define H0    1024
#define H1    512
#define H2    256
#define OUTD  7
#define G0    (4*H0)
#define NTICK (SEQ + 2)

// Persistent cooperative partition: one CTA per SM (smem-bound), 146 <= 148.
#define NCTA_L0 74
#define NCTA_L1 57
#define NCTA_L2 15
#define NCTA    (NCTA_L0 + NCTA_L1 + NCTA_L2)
#define EPC_L0  14   // elements per CTA, layer 0: 14*4*1024*4B = 229376 B smem
#define EPC_L1  9    // 9*4*1536*4B  = 221184 B
#define EPC_L2  18   // 18*4*768*4B  = 221184 B
#define SMEM_BYTES (EPC_L0 * 4 * H0 * 4)   // 229376 <= 232448 opt-in limit

#define FLAG_PAD 32  // 128B per arrival flag -> distinct L2 lines

// Scratch (static device arrays — no runtime allocation).
// h histories: slot (t+1) holds h(t); slot 0 holds the zero initial state and
// is NEVER written -> stays zero across graph replays. All other slots are
// written exactly once per replay BEFORE being read.
__device__ __align__(16) float g_xg0[SEQ * G0];          // 16 MB: Wih0@x + bih0 + bhh0
__device__ __align__(16) float g_h0h[(SEQ + 1) * H0];
__device__ __align__(16) float g_h1h[(SEQ + 1) * H1];
__device__ __align__(16) float g_h2h[(SEQ + 1) * H2];
__device__ int g_arrive[NCTA * FLAG_PAD];                // per-CTA monotonic arrival flags
__device__ int g_release;                                // monotonic release word

__device__ __forceinline__ float sigf(float x) { return 1.0f / (1.0f + expf(-x)); }

// ---------------------------------------------------------------------------
// Grid barrier: flags + broadcast release.
//  - arrival:  CTA b writes g_arrive[b*PAD] = k+1   (146 distinct lines)
//  - detect:   CTA 0, thread i polls flag i          (1 reader per line)
//  - release:  CTA 0 thread 0 writes g_release=k+1; others poll read-only
//              with nanosleep backoff (keeps the release write unobstructed).
// Monotonic counters, zeroed by reset_kernel each replay.
// ---------------------------------------------------------------------------
__device__ __forceinline__ void grid_bar(int k) {
    const int need = k + 1;
    __threadfence();
    __syncthreads();
    if (blockIdx.x == 0) {
        if (threadIdx.x > 0 && threadIdx.x < NCTA) {
            while (*(volatile int*)(g_arrive + threadIdx.x * FLAG_PAD) < need) {
                __nanosleep(20);
            }
        }
        __syncthreads();
        if (threadIdx.x == 0) {
            __threadfence();
            *(volatile int*)&g_release = need;
        }
    } else {
        if (threadIdx.x == 0) {
            *(volatile int*)(g_arrive + blockIdx.x * FLAG_PAD) = need;
            while (*(volatile int*)&g_release < need) {
                __nanosleep(30);
            }
            __threadfence();
        }
    }
    __syncthreads();
}

// ---------------------------------------------------------------------------
// Kernel 1: XG0[t][r] = sum_e emb[tok[t]][e] * Wih0[r][e] + bih0[r] + bhh0[r]
// 64x64 tile GEMM, fused embedding gather (only batch element 63 is live).
// ---------------------------------------------------------------------------
__global__ void xgemm_kernel(const int* __restrict__ tokens,
                             const float* __restrict__ emb,
                             const float* __restrict__ Wih0,
                             const float* __restrict__ bih0,
                             const float* __restrict__ bhh0) {
    __shared__ float As[64][33];
    __shared__ float Bs[64][33];
    __shared__ int toks[64];
    const int t0 = blockIdx.y * 64;
    const int r0 = blockIdx.x * 64;
    const int tid = threadIdx.x;
    if (tid < 64) toks[tid] = tokens[(t0 + tid) * TB + (TB - 1)];
    __syncthreads();

    float acc[4][4] = {};
    const int ty = tid >> 4, tx = tid & 15;

    for (int k0 = 0; k0 < EMBD; k0 += 32) {
#pragma unroll
        for (int l = 0; l < 2; l++) {
            int f4 = tid + l * 256;
            int row = f4 >> 3;
            int c4 = f4 & 7;
            float4 a = *(const float4*)(emb + (size_t)toks[row] * EMBD + k0 + c4 * 4);
            As[row][c4 * 4 + 0] = a.x; As[row][c4 * 4 + 1] = a.y;
            As[row][c4 * 4 + 2] = a.z; As[row][c4 * 4 + 3] = a.w;
            float4 b = *(const float4*)(Wih0 + (size_t)(r0 + row) * EMBD + k0 + c4 * 4);
            Bs[row][c4 * 4 + 0] = b.x; Bs[row][c4 * 4 + 1] = b.y;
            Bs[row][c4 * 4 + 2] = b.z; Bs[row][c4 * 4 + 3] = b.w;
        }
        __syncthreads();
#pragma unroll
        for (int kk = 0; kk < 32; kk++) {
            float a[4], b[4];
#pragma unroll
            for (int i = 0; i < 4; i++) a[i] = As[ty * 4 + i][kk];
#pragma unroll
            for (int j = 0; j < 4; j++) b[j] = Bs[tx * 4 + j][kk];
#pragma unroll
            for (int i = 0; i < 4; i++)
#pragma unroll
                for (int j = 0; j < 4; j++) acc[i][j] += a[i] * b[j];
        }
        __syncthreads();
    }
#pragma unroll
    for (int i = 0; i < 4; i++) {
#pragma unroll
        for (int j = 0; j < 4; j++) {
            int r = r0 + tx * 4 + j;
            int t = t0 + ty * 4 + i;
            g_xg0[(size_t)t * G0 + r] = acc[i][j] + bih0[r] + bhh0[r];
        }
    }
}

// ---------------------------------------------------------------------------
// Kernel 2: reset barrier state (each launch/replay; ordered by kernel bound)
// ---------------------------------------------------------------------------
__global__ void reset_kernel() {
    int i = blockIdx.x * blockDim.x + threadIdx.x;
    if (i < NCTA * FLAG_PAD) g_arrive[i] = 0;
    if (i == 0) g_release = 0;
}

// ---------------------------------------------------------------------------
// Kernel 3: cooperative pipelined recurrence with SMEM-resident weights.
// Tick k: L0 computes t=k, L1 t=k-1, L2 t=k-2. One grid_bar per tick.
// One warp per hidden element (L2: two); weights staged once into smem.
// Biases added AFTER the warp butterfly reduction.
// (Cooperative launch retained solely for the co-residency guarantee.)
// ---------------------------------------------------------------------------
__global__ void __launch_bounds__(512, 1) recur_coop(
    const float* __restrict__ Whh0,
    const float* __restrict__ Wih1, const float* __restrict__ Whh1,
    const float* __restrict__ bih1, const float* __restrict__ bhh1,
    const float* __restrict__ Wih2, const float* __restrict__ Whh2,
    const float* __restrict__ bih2, const float* __restrict__ bhh2)
{
    extern __shared__ float s_w[];

    const int b = blockIdx.x;
    const int tid = threadIdx.x;
    const int w = tid >> 5;
    const int lane = tid & 31;

    int role, base, count;
    if (b < NCTA_L0)                { role = 0; base = b * EPC_L0;              count = min(EPC_L0, H0 - base); }
    else if (b < NCTA_L0 + NCTA_L1) { role = 1; base = (b - NCTA_L0) * EPC_L1;  count = min(EPC_L1, H1 - base); }
    else                            { role = 2; base = (b - NCTA_L0 - NCTA_L1) * EPC_L2; count = min(EPC_L2, H2 - base); }

    // ---- Stage weights into smem (once) ----
    {
        float4* dst = (float4*)s_w;
        if (role == 0) {
            const int nf4 = count * 1024;            // slot: 4 gates x 256 f4
            for (int i = tid; i < nf4; i += 512) {
                int s = i >> 10, g = (i >> 8) & 3, c = i & 255;
                dst[i] = *((const float4*)(Whh0 + (size_t)(g * H0 + base + s) * H0) + c);
            }
        } else if (role == 1) {
            const int nf4 = count * 1536;            // slot: 4 gates x (256 ih + 128 hh) f4
            for (int i = tid; i < nf4; i += 512) {
                int s = i / 1536, rem = i - s * 1536;
                int g = rem / 384, q = rem - g * 384;
                int j = base + s;
                if (q < 256)
                    dst[i] = *((const float4*)(Wih1 + (size_t)(g * H1 + j) * H0) + q);
                else
                    dst[i] = *((const float4*)(Whh1 + (size_t)(g * H1 + j) * H1) + (q - 256));
            }
        } else {
            const int nf4 = count * 768;             // slot: 4 gates x (128 ih + 64 hh) f4
            for (int i = tid; i < nf4; i += 512) {
                int s = i / 768, rem = i - s * 768;
                int g = rem / 192, q = rem - g * 192;
                int j = base + s;
                if (q < 128)
                    dst[i] = *((const float4*)(Wih2 + (size_t)(g * H2 + j) * H1) + q);
                else
                    dst[i] = *((const float4*)(Whh2 + (size_t)(g * H2 + j) * H2) + (q - 128));
            }
        }
    }
    __syncthreads();

    // ---- Per-warp state ----
    const int j0 = base + w;                     // roles 0/1 element
    const bool act01 = (w < count);
    float c_state = 0.0f;                        // roles 0/1
    float bsum[4] = {0.f, 0.f, 0.f, 0.f};        // role 1 bias
    float c2[2] = {0.f, 0.f};                    // role 2 (two elements/warp)
    float bb2[2][4];

    if (role == 1 && act01) {
#pragma unroll
        for (int g = 0; g < 4; g++)
            bsum[g] = __ldg(bih1 + g * H1 + j0) + __ldg(bhh1 + g * H1 + j0);
    } else if (role == 2) {
#pragma unroll
        for (int ee = 0; ee < 2; ee++) {
            int e = w + ee * 16;
            if (e < count) {
                int j = base + e;
#pragma unroll
                for (int g = 0; g < 4; g++)
                    bb2[ee][g] = __ldg(bih2 + g * H2 + j) + __ldg(bhh2 + g * H2 + j);
            } else {
                bb2[ee][0] = bb2[ee][1] = bb2[ee][2] = bb2[ee][3] = 0.f;
            }
        }
    }

    for (int k = 0; k < NTICK; k++) {
        if (role == 0) {
            // -------- Layer 0: time t = k --------
            if (act01 && k < SEQ) {
                const float4* hp = (const float4*)(g_h0h + (size_t)k * H0);
                float4 h4[8];
#pragma unroll
                for (int m = 0; m < 8; m++) h4[m] = __ldcg(hp + m * 32 + lane);
                float xg[4];
#pragma unroll
                for (int g = 0; g < 4; g++)
                    xg[g] = __ldg(g_xg0 + (size_t)k * G0 + g * H0 + j0);
                const float4* wb = (const float4*)s_w + (size_t)w * 1024;
                float a[4];
#pragma unroll
                for (int g = 0; g < 4; g++) {
                    const float4* wg = wb + g * 256;
                    float s = 0.f;
#pragma unroll
                    for (int m = 0; m < 8; m++) {
                        float4 w4 = wg[m * 32 + lane];
                        s += w4.x * h4[m].x + w4.y * h4[m].y + w4.z * h4[m].z + w4.w * h4[m].w;
                    }
                    a[g] = s;
                }
#pragma unroll
                for (int off = 16; off > 0; off >>= 1)
#pragma unroll
                    for (int g = 0; g < 4; g++)
                        a[g] += __shfl_xor_sync(0xffffffffu, a[g], off);
#pragma unroll
                for (int g = 0; g < 4; g++) a[g] += xg[g];
                float ii = sigf(a[0]), ff = sigf(a[1]), gg = tanhf(a[2]), oo = sigf(a[3]);
                c_state = ff * c_state + ii * gg;
                float hval = oo * tanhf(c_state);
                if (lane == 0) g_h0h[(size_t)(k + 1) * H0 + j0] = hval;
            }
        } else if (role == 1) {
            // -------- Layer 1: time t = k-1 --------
            if (act01 && k >= 1 && k <= SEQ) {
                const float4* h0p = (const float4*)(g_h0h + (size_t)k * H0);
                const float4* h1p = (const float4*)(g_h1h + (size_t)(k - 1) * H1);
                float4 hA[8], hB[4];
#pragma unroll
                for (int m = 0; m < 8; m++) hA[m] = __ldcg(h0p + m * 32 + lane);
#pragma unroll
                for (int m = 0; m < 4; m++) hB[m] = __ldcg(h1p + m * 32 + lane);
                const float4* wb = (const float4*)s_w + (size_t)w * 1536;
                float a[4];
#pragma unroll
                for (int g = 0; g < 4; g++) {
                    const float4* wi = wb + g * 384;
                    const float4* wh = wi + 256;
                    float s = 0.f;
#pragma unroll
                    for (int m = 0; m < 8; m++) {
                        float4 w4 = wi[m * 32 + lane];
                        s += w4.x * hA[m].x + w4.y * hA[m].y + w4.z * hA[m].z + w4.w * hA[m].w;
                    }
#pragma unroll
                    for (int m = 0; m < 4; m++) {
                        float4 w4 = wh[m * 32 + lane];
                        s += w4.x * hB[m].x + w4.y * hB[m].y + w4.z * hB[m].z + w4.w * hB[m].w;
                    }
                    a[g] = s;
                }
#pragma unroll
                for (int off = 16; off > 0; off >>= 1)
#pragma unroll
                    for (int g = 0; g < 4; g++)
                        a[g] += __shfl_xor_sync(0xffffffffu, a[g], off);
#pragma unroll
                for (int g = 0; g < 4; g++) a[g] += bsum[g];   // AFTER reduction
                float ii = sigf(a[0]), ff = sigf(a[1]), gg = tanhf(a[2]), oo = sigf(a[3]);
                c_state = ff * c_state + ii * gg;
                float hval = oo * tanhf(c_state);
                if (lane == 0) g_h1h[(size_t)k * H1 + j0] = hval;
            }
        } else {
            // -------- Layer 2: time t = k-2 (two elements per warp) --------
            if (k >= 2 && k <= SEQ + 1) {
                const float4* h1p = (const float4*)(g_h1h + (size_t)(k - 1) * H1);
                const float4* h2p = (const float4*)(g_h2h + (size_t)(k - 2) * H2);
                float4 hA[4], hB[2];
#pragma unroll
                for (int m = 0; m < 4; m++) hA[m] = __ldcg(h1p + m * 32 + lane);
#pragma unroll
                for (int m = 0; m < 2; m++) hB[m] = __ldcg(h2p + m * 32 + lane);
#pragma unroll
                for (int ee = 0; ee < 2; ee++) {
                    int e = w + ee * 16;
                    if (e < count) {
                        const float4* wb = (const float4*)s_w + (size_t)e * 768;
                        float a[4];
#pragma unroll
                        for (int g = 0; g < 4; g++) {
                            const float4* wi = wb + g * 192;
                            const float4* wh = wi + 128;
                            float s = 0.f;
#pragma unroll
                            for (int m = 0; m < 4; m++) {
                                float4 w4 = wi[m * 32 + lane];
                                s += w4.x * hA[m].x + w4.y * hA[m].y + w4.z * hA[m].z + w4.w * hA[m].w;
                            }
#pragma unroll
                            for (int m = 0; m < 2; m++) {
                                float4 w4 = wh[m * 32 + lane];
                                s += w4.x * hB[m].x + w4.y * hB[m].y + w4.z * hB[m].z + w4.w * hB[m].w;
                            }
                            a[g] = s;
                        }
#pragma unroll
                        for (int off = 16; off > 0; off >>= 1)
#pragma unroll
                            for (int g = 0; g < 4; g++)
                                a[g] += __shfl_xor_sync(0xffffffffu, a[g], off);
#pragma unroll
                        for (int g = 0; g < 4; g++) a[g] += bb2[ee][g];   // AFTER reduction
                        float ii = sigf(a[0]), ff = sigf(a[1]), gg = tanhf(a[2]), oo = sigf(a[3]);
                        c2[ee] = ff * c2[ee] + ii * gg;
                        float hval = oo * tanhf(c2[ee]);
                        if (lane == 0) g_h2h[(size_t)(k - 1) * H2 + base + e] = hval;
                    }
                }
            }
        }
        grid_bar(k);   // single call site for the whole grid
    }
}

// ---------------------------------------------------------------------------
// Kernel 4: out[t][o] = h2(t) . Wlin[o] + blin[o]   (1024 x 7 x 256)
// ---------------------------------------------------------------------------
__global__ void linout_kernel(const float* __restrict__ Wlin,
                              const float* __restrict__ blin,
                              float* __restrict__ out) {
    const int w = threadIdx.x >> 5, lane = threadIdx.x & 31;
    const int t = blockIdx.x * 4 + w;
    float hv[8];
#pragma unroll
    for (int m = 0; m < 8; m++) hv[m] = g_h2h[(size_t)(t + 1) * H2 + m * 32 + lane];
#pragma unroll
    for (int o = 0; o < OUTD; o++) {
        float acc = 0.f;
#pragma unroll
        for (int m = 0; m < 8; m++)
            acc += hv[m] * __ldg(Wlin + o * H2 + m * 32 + lane);
#pragma unroll
        for (int off = 16; off > 0; off >>= 1)
            acc += __shfl_xor_sync(0xffffffffu, acc, off);
        if (lane == 0) out[t * OUTD + o] = acc + __ldg(blin + o);
    }
}

// ---------------------------------------------------------------------------
extern "C" void kernel_launch(void* const* d_in, const int* in_sizes, int n_in,
                              void* d_out, int out_size) {
    const int*   tokens = (const int*)d_in[0];
    const float* emb  = (const float*)d_in[1];
    const float* Wih0 = (const float*)d_in[2];
    const float* Whh0 = (const float*)d_in[3];
    const float* bih0 = (const float*)d_in[4];
    const float* bhh0 = (const float*)d_in[5];
    const float* Wih1 = (const float*)d_in[6];
    const float* Whh1 = (const float*)d_in[7];
    const float* bih1 = (const float*)d_in[8];
    const float* bhh1 = (const float*)d_in[9];
    const float* Wih2 = (const float*)d_in[10];
    const float* Whh2 = (const float*)d_in[11];
    const float* bih2 = (const float*)d_in[12];
    const float* bhh2 = (const float*)d_in[13];
    const float* Wlin = (const float*)d_in[14];
    const float* blin = (const float*)d_in[15];
    float* out = (float*)d_out;

    cudaFuncSetAttribute(recur_coop, cudaFuncAttributeMaxDynamicSharedMemorySize, SMEM_BYTES);

    xgemm_kernel<<<dim3(G0 / 64, SEQ / 64), 256>>>(tokens, emb, Wih0, bih0, bhh0);
    reset_kernel<<<5, 1024>>>();

    const float* a0 = Whh0;
    const float* a1 = Wih1; const float* a2 = Whh1;
    const float* a3 = bih1; const float* a4 = bhh1;
    const float* a5 = Wih2; const float* a6 = Whh2;
    const float* a7 = bih2; const float* a8 = bhh2;
    void* args[] = { (void*)&a0, (void*)&a1, (void*)&a2, (void*)&a3, (void*)&a4,
                     (void*)&a5, (void*)&a6, (void*)&a7, (void*)&a8 };
    cudaLaunchCooperativeKernel((void*)recur_coop,
                                dim3(NCTA), dim3(512), args, SMEM_BYTES, (cudaStream_t)0);

    linout_kernel<<<SEQ / 4, 128>>>(Wlin, blin, out);
}

// round 12
// speedup vs baseline: 1.0322x; 1.0322x over previous
#include <cuda_runtime.h>
#include <cooperative_groups.h>
#include <math.h>

namespace cg = cooperative_groups;

// Problem constants
#define SEQ   1024
#define TB    64
#define EMBD  512
#define H0    1024
#define H1    512
#define H2    256
#define OUTD  7
#define G0    (4*H0)

// Persistent cooperative partition: one CTA per SM (smem-bound), 146 <= 148.
#define NCTA_L0 74
#define NCTA_L1 57
#define NCTA_L2 15
#define NCTA    (NCTA_L0 + NCTA_L1 + NCTA_L2)
#define EPC_L0  14   // elements per CTA, layer 0: 14*4*1024*4B = 229376 B smem
#define EPC_L1  9    // 9*4*1536*4B  = 221184 B
#define EPC_L2  18   // 18*4*768*4B  = 221184 B
#define SMEM_BYTES (EPC_L0 * 4 * H0 * 4)   // 229376 <= 232448 opt-in limit

#define FLAG_PAD 32  // 128B per flag -> distinct L2 lines

// Scratch (static device arrays — no runtime allocation).
// h histories: slot (t+1) holds h(t); slot 0 holds the zero initial state and
// is NEVER written -> stays zero across graph replays. All other slots are
// written exactly once per replay BEFORE being read (no WAR hazards).
__device__ __align__(16) float g_xg0[SEQ * G0];          // 16 MB: Wih0@x + bih0 + bhh0
__device__ __align__(16) float g_h0h[(SEQ + 1) * H0];
__device__ __align__(16) float g_h1h[(SEQ + 1) * H1];
__device__ __align__(16) float g_h2h[(SEQ + 1) * H2];
// g_flag[b*FLAG_PAD] = number of completed steps of CTA b (monotonic per replay)
__device__ int g_flag[NCTA * FLAG_PAD];

__device__ __forceinline__ float sigf(float x) { return 1.0f / (1.0f + expf(-x)); }

// ---------------------------------------------------------------------------
// Distributed dependency wait: warp 0 polls exactly the flags this CTA's next
// step depends on. No central detect/release — detection is one L2 round trip
// after the last producer's flag store. lo..hi is the flag index range;
// flags < split need >= t_hi, flags >= split need >= t_lo.
// ---------------------------------------------------------------------------
__device__ __forceinline__ void dep_wait(int lo, int hi, int split,
                                         int t_hi, int t_lo) {
    if (threadIdx.x < 32) {
        const int lane = threadIdx.x;
        bool ok;
        do {
            ok = true;
            for (int i = lo + lane; i < hi; i += 32) {
                int tgt = (i < split) ? t_hi : t_lo;
                if (*(volatile int*)(g_flag + i * FLAG_PAD) < tgt) ok = false;
            }
            ok = __all_sync(0xffffffffu, ok);
            if (!ok) __nanosleep(30);
        } while (!ok);
        __threadfence();
    }
    __syncthreads();
}

// Publish completion of step t (flag := t+1). Call AFTER all h stores.
__device__ __forceinline__ void publish(int b, int t) {
    __threadfence();
    __syncthreads();
    if (threadIdx.x == 0)
        *(volatile int*)(g_flag + b * FLAG_PAD) = t + 1;
}

// ---------------------------------------------------------------------------
// Kernel 1: XG0[t][r] = sum_e emb[tok[t]][e] * Wih0[r][e] + bih0[r] + bhh0[r]
// 64x64 tile GEMM, fused embedding gather (only batch element 63 is live).
// ---------------------------------------------------------------------------
__global__ void xgemm_kernel(const int* __restrict__ tokens,
                             const float* __restrict__ emb,
                             const float* __restrict__ Wih0,
                             const float* __restrict__ bih0,
                             const float* __restrict__ bhh0) {
    __shared__ float As[64][33];
    __shared__ float Bs[64][33];
    __shared__ int toks[64];
    const int t0 = blockIdx.y * 64;
    const int r0 = blockIdx.x * 64;
    const int tid = threadIdx.x;
    if (tid < 64) toks[tid] = tokens[(t0 + tid) * TB + (TB - 1)];
    __syncthreads();

    float acc[4][4] = {};
    const int ty = tid >> 4, tx = tid & 15;

    for (int k0 = 0; k0 < EMBD; k0 += 32) {
#pragma unroll
        for (int l = 0; l < 2; l++) {
            int f4 = tid + l * 256;
            int row = f4 >> 3;
            int c4 = f4 & 7;
            float4 a = *(const float4*)(emb + (size_t)toks[row] * EMBD + k0 + c4 * 4);
            As[row][c4 * 4 + 0] = a.x; As[row][c4 * 4 + 1] = a.y;
            As[row][c4 * 4 + 2] = a.z; As[row][c4 * 4 + 3] = a.w;
            float4 b = *(const float4*)(Wih0 + (size_t)(r0 + row) * EMBD + k0 + c4 * 4);
            Bs[row][c4 * 4 + 0] = b.x; Bs[row][c4 * 4 + 1] = b.y;
            Bs[row][c4 * 4 + 2] = b.z; Bs[row][c4 * 4 + 3] = b.w;
        }
        __syncthreads();
#pragma unroll
        for (int kk = 0; kk < 32; kk++) {
            float a[4], b[4];
#pragma unroll
            for (int i = 0; i < 4; i++) a[i] = As[ty * 4 + i][kk];
#pragma unroll
            for (int j = 0; j < 4; j++) b[j] = Bs[tx * 4 + j][kk];
#pragma unroll
            for (int i = 0; i < 4; i++)
#pragma unroll
                for (int j = 0; j < 4; j++) acc[i][j] += a[i] * b[j];
        }
        __syncthreads();
    }
#pragma unroll
    for (int i = 0; i < 4; i++) {
#pragma unroll
        for (int j = 0; j < 4; j++) {
            int r = r0 + tx * 4 + j;
            int t = t0 + ty * 4 + i;
            g_xg0[(size_t)t * G0 + r] = acc[i][j] + bih0[r] + bhh0[r];
        }
    }
}

// ---------------------------------------------------------------------------
// Kernel 2: reset flags (each launch/replay; ordered by kernel boundary)
// ---------------------------------------------------------------------------
__global__ void reset_kernel() {
    int i = blockIdx.x * blockDim.x + threadIdx.x;
    if (i < NCTA * FLAG_PAD) g_flag[i] = 0;
}

// ---------------------------------------------------------------------------
// Kernel 3: persistent recurrence, NO global barrier. Layers are decoupled:
// each CTA waits only on the flags its next step actually depends on.
//   L0 step t: L0 flags >= t
//   L1 step t: L0 flags >= t+1, L1 flags >= t
//   L2 step t: L1 flags >= t+1, L2 flags >= t
// Weights SMEM-resident; biases added AFTER the warp butterfly reduction.
// (Cooperative launch retained solely for the co-residency guarantee.)
// ---------------------------------------------------------------------------
__global__ void __launch_bounds__(512, 1) recur_coop(
    const float* __restrict__ Whh0,
    const float* __restrict__ Wih1, const float* __restrict__ Whh1,
    const float* __restrict__ bih1, const float* __restrict__ bhh1,
    const float* __restrict__ Wih2, const float* __restrict__ Whh2,
    const float* __restrict__ bih2, const float* __restrict__ bhh2)
{
    extern __shared__ float s_w[];

    const int b = blockIdx.x;
    const int tid = threadIdx.x;
    const int w = tid >> 5;
    const int lane = tid & 31;

    int role, base, count;
    if (b < NCTA_L0)                { role = 0; base = b * EPC_L0;              count = min(EPC_L0, H0 - base); }
    else if (b < NCTA_L0 + NCTA_L1) { role = 1; base = (b - NCTA_L0) * EPC_L1;  count = min(EPC_L1, H1 - base); }
    else                            { role = 2; base = (b - NCTA_L0 - NCTA_L1) * EPC_L2; count = min(EPC_L2, H2 - base); }

    // ---- Stage weights into smem (once) ----
    {
        float4* dst = (float4*)s_w;
        if (role == 0) {
            const int nf4 = count * 1024;            // slot: 4 gates x 256 f4
            for (int i = tid; i < nf4; i += 512) {
                int s = i >> 10, g = (i >> 8) & 3, c = i & 255;
                dst[i] = *((const float4*)(Whh0 + (size_t)(g * H0 + base + s) * H0) + c);
            }
        } else if (role == 1) {
            const int nf4 = count * 1536;            // slot: 4 gates x (256 ih + 128 hh) f4
            for (int i = tid; i < nf4; i += 512) {
                int s = i / 1536, rem = i - s * 1536;
                int g = rem / 384, q = rem - g * 384;
                int j = base + s;
                if (q < 256)
                    dst[i] = *((const float4*)(Wih1 + (size_t)(g * H1 + j) * H0) + q);
                else
                    dst[i] = *((const float4*)(Whh1 + (size_t)(g * H1 + j) * H1) + (q - 256));
            }
        } else {
            const int nf4 = count * 768;             // slot: 4 gates x (128 ih + 64 hh) f4
            for (int i = tid; i < nf4; i += 512) {
                int s = i / 768, rem = i - s * 768;
                int g = rem / 192, q = rem - g * 192;
                int j = base + s;
                if (q < 128)
                    dst[i] = *((const float4*)(Wih2 + (size_t)(g * H2 + j) * H1) + q);
                else
                    dst[i] = *((const float4*)(Whh2 + (size_t)(g * H2 + j) * H2) + (q - 128));
            }
        }
    }
    __syncthreads();

    // ---- Per-warp state ----
    const int j0 = base + w;                     // roles 0/1 element
    const bool act01 = (w < count);
    float c_state = 0.0f;                        // roles 0/1
    float bsum[4] = {0.f, 0.f, 0.f, 0.f};        // role 1 bias
    float c2[2] = {0.f, 0.f};                    // role 2 (two elements/warp)
    float bb2[2][4];

    if (role == 1 && act01) {
#pragma unroll
        for (int g = 0; g < 4; g++)
            bsum[g] = __ldg(bih1 + g * H1 + j0) + __ldg(bhh1 + g * H1 + j0);
    } else if (role == 2) {
#pragma unroll
        for (int ee = 0; ee < 2; ee++) {
            int e = w + ee * 16;
            if (e < count) {
                int j = base + e;
#pragma unroll
                for (int g = 0; g < 4; g++)
                    bb2[ee][g] = __ldg(bih2 + g * H2 + j) + __ldg(bhh2 + g * H2 + j);
            } else {
                bb2[ee][0] = bb2[ee][1] = bb2[ee][2] = bb2[ee][3] = 0.f;
            }
        }
    }

    if (role == 0) {
        // ================= Layer 0 loop =================
        for (int t = 0; t < SEQ; t++) {
            // need h0(t-1): all L0 flags >= t  (t=0 trivially true)
            if (t > 0) dep_wait(0, NCTA_L0, NCTA_L0, t, t);
            else __syncthreads();
            if (act01) {
                const float4* hp = (const float4*)(g_h0h + (size_t)t * H0);
                float4 h4[8];
#pragma unroll
                for (int m = 0; m < 8; m++) h4[m] = __ldcg(hp + m * 32 + lane);
                float xg[4];
#pragma unroll
                for (int g = 0; g < 4; g++)
                    xg[g] = __ldg(g_xg0 + (size_t)t * G0 + g * H0 + j0);
                const float4* wb = (const float4*)s_w + (size_t)w * 1024;
                float a[4];
#pragma unroll
                for (int g = 0; g < 4; g++) {
                    const float4* wg = wb + g * 256;
                    float s = 0.f;
#pragma unroll
                    for (int m = 0; m < 8; m++) {
                        float4 w4 = wg[m * 32 + lane];
                        s += w4.x * h4[m].x + w4.y * h4[m].y + w4.z * h4[m].z + w4.w * h4[m].w;
                    }
                    a[g] = s;
                }
#pragma unroll
                for (int off = 16; off > 0; off >>= 1)
#pragma unroll
                    for (int g = 0; g < 4; g++)
                        a[g] += __shfl_xor_sync(0xffffffffu, a[g], off);
#pragma unroll
                for (int g = 0; g < 4; g++) a[g] += xg[g];
                float ii = sigf(a[0]), ff = sigf(a[1]), gg = tanhf(a[2]), oo = sigf(a[3]);
                c_state = ff * c_state + ii * gg;
                float hval = oo * tanhf(c_state);
                if (lane == 0) g_h0h[(size_t)(t + 1) * H0 + j0] = hval;
            }
            publish(b, t);
        }
    } else if (role == 1) {
        // ================= Layer 1 loop =================
        for (int t = 0; t < SEQ; t++) {
            // need h0(t): L0 flags >= t+1; and h1(t-1): L1 flags >= t
            dep_wait(0, NCTA_L0 + NCTA_L1, NCTA_L0, t + 1, t);
            if (act01) {
                const float4* h0p = (const float4*)(g_h0h + (size_t)(t + 1) * H0);
                const float4* h1p = (const float4*)(g_h1h + (size_t)t * H1);
                float4 hA[8], hB[4];
#pragma unroll
                for (int m = 0; m < 8; m++) hA[m] = __ldcg(h0p + m * 32 + lane);
#pragma unroll
                for (int m = 0; m < 4; m++) hB[m] = __ldcg(h1p + m * 32 + lane);
                const float4* wb = (const float4*)s_w + (size_t)w * 1536;
                float a[4];
#pragma unroll
                for (int g = 0; g < 4; g++) {
                    const float4* wi = wb + g * 384;
                    const float4* wh = wi + 256;
                    float s = 0.f;
#pragma unroll
                    for (int m = 0; m < 8; m++) {
                        float4 w4 = wi[m * 32 + lane];
                        s += w4.x * hA[m].x + w4.y * hA[m].y + w4.z * hA[m].z + w4.w * hA[m].w;
                    }
#pragma unroll
                    for (int m = 0; m < 4; m++) {
                        float4 w4 = wh[m * 32 + lane];
                        s += w4.x * hB[m].x + w4.y * hB[m].y + w4.z * hB[m].z + w4.w * hB[m].w;
                    }
                    a[g] = s;
                }
#pragma unroll
                for (int off = 16; off > 0; off >>= 1)
#pragma unroll
                    for (int g = 0; g < 4; g++)
                        a[g] += __shfl_xor_sync(0xffffffffu, a[g], off);
#pragma unroll
                for (int g = 0; g < 4; g++) a[g] += bsum[g];   // AFTER reduction
                float ii = sigf(a[0]), ff = sigf(a[1]), gg = tanhf(a[2]), oo = sigf(a[3]);
                c_state = ff * c_state + ii * gg;
                float hval = oo * tanhf(c_state);
                if (lane == 0) g_h1h[(size_t)(t + 1) * H1 + j0] = hval;
            }
            publish(b, t);
        }
    } else {
        // ================= Layer 2 loop =================
        for (int t = 0; t < SEQ; t++) {
            // need h1(t): L1 flags >= t+1; and h2(t-1): L2 flags >= t
            dep_wait(NCTA_L0, NCTA, NCTA_L0 + NCTA_L1, t + 1, t);
            {
                const float4* h1p = (const float4*)(g_h1h + (size_t)(t + 1) * H1);
                const float4* h2p = (const float4*)(g_h2h + (size_t)t * H2);
                float4 hA[4], hB[2];
#pragma unroll
                for (int m = 0; m < 4; m++) hA[m] = __ldcg(h1p + m * 32 + lane);
#pragma unroll
                for (int m = 0; m < 2; m++) hB[m] = __ldcg(h2p + m * 32 + lane);
#pragma unroll
                for (int ee = 0; ee < 2; ee++) {
                    int e = w + ee * 16;
                    if (e < count) {
                        const float4* wb = (const float4*)s_w + (size_t)e * 768;
                        float a[4];
#pragma unroll
                        for (int g = 0; g < 4; g++) {
                            const float4* wi = wb + g * 192;
                            const float4* wh = wi + 128;
                            float s = 0.f;
#pragma unroll
                            for (int m = 0; m < 4; m++) {
                                float4 w4 = wi[m * 32 + lane];
                                s += w4.x * hA[m].x + w4.y * hA[m].y + w4.z * hA[m].z + w4.w * hA[m].w;
                            }
#pragma unroll
                            for (int m = 0; m < 2; m++) {
                                float4 w4 = wh[m * 32 + lane];
                                s += w4.x * hB[m].x + w4.y * hB[m].y + w4.z * hB[m].z + w4.w * hB[m].w;
                            }
                            a[g] = s;
                        }
#pragma unroll
                        for (int off = 16; off > 0; off >>= 1)
#pragma unroll
                            for (int g = 0; g < 4; g++)
                                a[g] += __shfl_xor_sync(0xffffffffu, a[g], off);
#pragma unroll
                        for (int g = 0; g < 4; g++) a[g] += bb2[ee][g];   // AFTER reduction
                        float ii = sigf(a[0]), ff = sigf(a[1]), gg = tanhf(a[2]), oo = sigf(a[3]);
                        c2[ee] = ff * c2[ee] + ii * gg;
                        float hval = oo * tanhf(c2[ee]);
                        if (lane == 0) g_h2h[(size_t)(t + 1) * H2 + base + e] = hval;
                    }
                }
            }
            publish(b, t);
        }
    }
}

// ---------------------------------------------------------------------------
// Kernel 4: out[t][o] = h2(t) . Wlin[o] + blin[o]   (1024 x 7 x 256)
// ---------------------------------------------------------------------------
__global__ void linout_kernel(const float* __restrict__ Wlin,
                              const float* __restrict__ blin,
                              float* __restrict__ out) {
    const int w = threadIdx.x >> 5, lane = threadIdx.x & 31;
    const int t = blockIdx.x * 4 + w;
    float hv[8];
#pragma unroll
    for (int m = 0; m < 8; m++) hv[m] = g_h2h[(size_t)(t + 1) * H2 + m * 32 + lane];
#pragma unroll
    for (int o = 0; o < OUTD; o++) {
        float acc = 0.f;
#pragma unroll
        for (int m = 0; m < 8; m++)
            acc += hv[m] * __ldg(Wlin + o * H2 + m * 32 + lane);
#pragma unroll
        for (int off = 16; off > 0; off >>= 1)
            acc += __shfl_xor_sync(0xffffffffu, acc, off);
        if (lane == 0) out[t * OUTD + o] = acc + __ldg(blin + o);
    }
}

// ---------------------------------------------------------------------------
extern "C" void kernel_launch(void* const* d_in, const int* in_sizes, int n_in,
                              void* d_out, int out_size) {
    const int*   tokens = (const int*)d_in[0];
    const float* emb  = (const float*)d_in[1];
    const float* Wih0 = (const float*)d_in[2];
    const float* Whh0 = (const float*)d_in[3];
    const float* bih0 = (const float*)d_in[4];
    const float* bhh0 = (const float*)d_in[5];
    const float* Wih1 = (const float*)d_in[6];
    const float* Whh1 = (const float*)d_in[7];
    const float* bih1 = (const float*)d_in[8];
    const float* bhh1 = (const float*)d_in[9];
    const float* Wih2 = (const float*)d_in[10];
    const float* Whh2 = (const float*)d_in[11];
    const float* bih2 = (const float*)d_in[12];
    const float* bhh2 = (const float*)d_in[13];
    const float* Wlin = (const float*)d_in[14];
    const float* blin = (const float*)d_in[15];
    float* out = (float*)d_out;

    cudaFuncSetAttribute(recur_coop, cudaFuncAttributeMaxDynamicSharedMemorySize, SMEM_BYTES);

    xgemm_kernel<<<dim3(G0 / 64, SEQ / 64), 256>>>(tokens, emb, Wih0, bih0, bhh0);
    reset_kernel<<<5, 1024>>>();

    const float* a0 = Whh0;
    const float* a1 = Wih1; const float* a2 = Whh1;
    const float* a3 = bih1; const float* a4 = bhh1;
    const float* a5 = Wih2; const float* a6 = Whh2;
    const float* a7 = bih2; const float* a8 = bhh2;
    void* args[] = { (void*)&a0, (void*)&a1, (void*)&a2, (void*)&a3, (void*)&a4,
                     (void*)&a5, (void*)&a6, (void*)&a7, (void*)&a8 };
    cudaLaunchCooperativeKernel((void*)recur_coop,
                                dim3(NCTA), dim3(512), args, SMEM_BYTES, (cudaStream_t)0);

    linout_kernel<<<SEQ / 4, 128>>>(Wlin, blin, out);
}

// round 13
// speedup vs baseline: 1.4050x; 1.3613x over previous
#include <cuda_runtime.h>
#include <cooperative_groups.h>
#include <cuda_bf16.h>
#include <math.h>

namespace cg = cooperative_groups;

// Problem constants
#define SEQ   1024
#define TB    64
#define EMBD  512
#define H0    1024
#define H1    512
#define H2    256
#define OUTD  7
#define G0    (4*H0)
#define NTICK (SEQ + 2)

// Persistent cooperative partition: one CTA per SM (smem-bound), 146 <= 148.
#define NCTA_L0 74
#define NCTA_L1 57
#define NCTA_L2 15
#define NCTA    (NCTA_L0 + NCTA_L1 + NCTA_L2)
#define EPC_L0  14   // elements per CTA, layer 0: 14*4*1024*2B = 114688 B smem
#define EPC_L1  9    // 9*4*1536*2B  = 110592 B
#define EPC_L2  18   // 18*4*768*2B  = 110592 B
// uint4 (8 bf16) strides per slot: L0 512, L1 768, L2 384
#define SMEM_BYTES (EPC_L0 * 512 * 16)     // 114688 B

// Scratch (static device arrays — no runtime allocation).
// h histories: slot (t+1) holds h(t); slot 0 holds the zero initial state and
// is NEVER written -> stays zero across graph replays. Write-once per replay.
__device__ __align__(16) float g_xg0[SEQ * G0];          // 16 MB: Wih0@x + bih0 + bhh0
__device__ __align__(16) float g_h0h[(SEQ + 1) * H0];
__device__ __align__(16) float g_h1h[(SEQ + 1) * H1];
__device__ __align__(16) float g_h2h[(SEQ + 1) * H2];

__device__ __forceinline__ float sigf(float x) { return 1.0f / (1.0f + expf(-x)); }

// fp32 pair -> packed bf16x2 (as uint32)
__device__ __forceinline__ unsigned int pack_bf2(float x, float y) {
    __nv_bfloat162 t = __floats2bfloat162_rn(x, y);
    return *reinterpret_cast<unsigned int*>(&t);
}
// packed bf16x2 -> fp32 pair
__device__ __forceinline__ float2 unpack_bf2(unsigned int u) {
    __nv_bfloat162 t = *reinterpret_cast<__nv_bfloat162*>(&u);
    return __bfloat1622float2(t);
}

// ---------------------------------------------------------------------------
// Kernel 1: XG0[t][r] = sum_e emb[tok[t]][e] * Wih0[r][e] + bih0[r] + bhh0[r]
// 64x64 tile GEMM, fused embedding gather (only batch element 63 is live).
// ---------------------------------------------------------------------------
__global__ void xgemm_kernel(const int* __restrict__ tokens,
                             const float* __restrict__ emb,
                             const float* __restrict__ Wih0,
                             const float* __restrict__ bih0,
                             const float* __restrict__ bhh0) {
    __shared__ float As[64][33];
    __shared__ float Bs[64][33];
    __shared__ int toks[64];
    const int t0 = blockIdx.y * 64;
    const int r0 = blockIdx.x * 64;
    const int tid = threadIdx.x;
    if (tid < 64) toks[tid] = tokens[(t0 + tid) * TB + (TB - 1)];
    __syncthreads();

    float acc[4][4] = {};
    const int ty = tid >> 4, tx = tid & 15;

    for (int k0 = 0; k0 < EMBD; k0 += 32) {
#pragma unroll
        for (int l = 0; l < 2; l++) {
            int f4 = tid + l * 256;
            int row = f4 >> 3;
            int c4 = f4 & 7;
            float4 a = *(const float4*)(emb + (size_t)toks[row] * EMBD + k0 + c4 * 4);
            As[row][c4 * 4 + 0] = a.x; As[row][c4 * 4 + 1] = a.y;
            As[row][c4 * 4 + 2] = a.z; As[row][c4 * 4 + 3] = a.w;
            float4 b = *(const float4*)(Wih0 + (size_t)(r0 + row) * EMBD + k0 + c4 * 4);
            Bs[row][c4 * 4 + 0] = b.x; Bs[row][c4 * 4 + 1] = b.y;
            Bs[row][c4 * 4 + 2] = b.z; Bs[row][c4 * 4 + 3] = b.w;
        }
        __syncthreads();
#pragma unroll
        for (int kk = 0; kk < 32; kk++) {
            float a[4], b[4];
#pragma unroll
            for (int i = 0; i < 4; i++) a[i] = As[ty * 4 + i][kk];
#pragma unroll
            for (int j = 0; j < 4; j++) b[j] = Bs[tx * 4 + j][kk];
#pragma unroll
            for (int i = 0; i < 4; i++)
#pragma unroll
                for (int j = 0; j < 4; j++) acc[i][j] += a[i] * b[j];
        }
        __syncthreads();
    }
#pragma unroll
    for (int i = 0; i < 4; i++) {
#pragma unroll
        for (int j = 0; j < 4; j++) {
            int r = r0 + tx * 4 + j;
            int t = t0 + ty * 4 + i;
            g_xg0[(size_t)t * G0 + r] = acc[i][j] + bih0[r] + bhh0[r];
        }
    }
}

// ---------------------------------------------------------------------------
// Kernel 2: cooperative pipelined recurrence, bf16-packed SMEM weights.
// Tick k: L0 computes t=k, L1 t=k-1, L2 t=k-2. ONE grid.sync() per tick.
// Weight layout: uint4 = 8 bf16 covering h-float4 pair (m, m+HALF) so the
// h register load pattern is identical to the fp32 version.
// Biases added AFTER the warp butterfly reduction.
// ---------------------------------------------------------------------------
__global__ void __launch_bounds__(512, 1) recur_coop(
    const float* __restrict__ Whh0,
    const float* __restrict__ Wih1, const float* __restrict__ Whh1,
    const float* __restrict__ bih1, const float* __restrict__ bhh1,
    const float* __restrict__ Wih2, const float* __restrict__ Whh2,
    const float* __restrict__ bih2, const float* __restrict__ bhh2)
{
    cg::grid_group grid = cg::this_grid();
    extern __shared__ uint4 s_w[];

    const int b = blockIdx.x;
    const int tid = threadIdx.x;
    const int w = tid >> 5;
    const int lane = tid & 31;

    int role, base, count;
    if (b < NCTA_L0)                { role = 0; base = b * EPC_L0;              count = min(EPC_L0, H0 - base); }
    else if (b < NCTA_L0 + NCTA_L1) { role = 1; base = (b - NCTA_L0) * EPC_L1;  count = min(EPC_L1, H1 - base); }
    else                            { role = 2; base = (b - NCTA_L0 - NCTA_L1) * EPC_L2; count = min(EPC_L2, H2 - base); }

    // ---- Stage weights into smem as packed bf16 (once) ----
    if (role == 0) {
        // slot stride 512 uint4; gate stride 128; uint4 q pairs f4 (q, q+128)
        const int n = count * 512;
        for (int i = tid; i < n; i += 512) {
            int s = i >> 9, rem = i & 511;
            int g = rem >> 7, q = rem & 127;
            const float4* row = (const float4*)(Whh0 + (size_t)(g * H0 + base + s) * H0);
            float4 a = row[q], c = row[q + 128];
            s_w[i] = make_uint4(pack_bf2(a.x, a.y), pack_bf2(a.z, a.w),
                                pack_bf2(c.x, c.y), pack_bf2(c.z, c.w));
        }
    } else if (role == 1) {
        // slot stride 768; gate stride 192; q<128: ih pair (q,q+128); q>=128: hh pair (q-128, q-64)
        const int n = count * 768;
        for (int i = tid; i < n; i += 512) {
            int s = i / 768, rem = i - s * 768;
            int g = rem / 192, q = rem - g * 192;
            int j = base + s;
            float4 a, c;
            if (q < 128) {
                const float4* row = (const float4*)(Wih1 + (size_t)(g * H1 + j) * H0);
                a = row[q]; c = row[q + 128];
            } else {
                const float4* row = (const float4*)(Whh1 + (size_t)(g * H1 + j) * H1);
                a = row[q - 128]; c = row[q - 64];
            }
            s_w[i] = make_uint4(pack_bf2(a.x, a.y), pack_bf2(a.z, a.w),
                                pack_bf2(c.x, c.y), pack_bf2(c.z, c.w));
        }
    } else {
        // slot stride 384; gate stride 96; q<64: ih pair (q,q+64); q>=64: hh pair (q-64, q-32)
        const int n = count * 384;
        for (int i = tid; i < n; i += 512) {
            int s = i / 384, rem = i - s * 384;
            int g = rem / 96, q = rem - g * 96;
            int j = base + s;
            float4 a, c;
            if (q < 64) {
                const float4* row = (const float4*)(Wih2 + (size_t)(g * H2 + j) * H1);
                a = row[q]; c = row[q + 64];
            } else {
                const float4* row = (const float4*)(Whh2 + (size_t)(g * H2 + j) * H2);
                a = row[q - 64]; c = row[q - 32];
            }
            s_w[i] = make_uint4(pack_bf2(a.x, a.y), pack_bf2(a.z, a.w),
                                pack_bf2(c.x, c.y), pack_bf2(c.z, c.w));
        }
    }
    __syncthreads();

    // ---- Per-warp state ----
    const int j0 = base + w;                     // roles 0/1 element
    const bool act01 = (w < count);
    float c_state = 0.0f;                        // roles 0/1
    float bsum[4] = {0.f, 0.f, 0.f, 0.f};        // role 1 bias
    float c2[2] = {0.f, 0.f};                    // role 2 (two elements/warp)
    float bb2[2][4];

    if (role == 1 && act01) {
#pragma unroll
        for (int g = 0; g < 4; g++)
            bsum[g] = __ldg(bih1 + g * H1 + j0) + __ldg(bhh1 + g * H1 + j0);
    } else if (role == 2) {
#pragma unroll
        for (int ee = 0; ee < 2; ee++) {
            int e = w + ee * 16;
            if (e < count) {
                int j = base + e;
#pragma unroll
                for (int g = 0; g < 4; g++)
                    bb2[ee][g] = __ldg(bih2 + g * H2 + j) + __ldg(bhh2 + g * H2 + j);
            } else {
                bb2[ee][0] = bb2[ee][1] = bb2[ee][2] = bb2[ee][3] = 0.f;
            }
        }
    }

    for (int k = 0; k < NTICK; k++) {
        if (role == 0) {
            // -------- Layer 0: time t = k --------
            if (act01 && k < SEQ) {
                const float4* hp = (const float4*)(g_h0h + (size_t)k * H0);
                float4 h4[8];
#pragma unroll
                for (int m = 0; m < 8; m++) h4[m] = __ldcg(hp + m * 32 + lane);
                float xg[4];
#pragma unroll
                for (int g = 0; g < 4; g++)
                    xg[g] = __ldg(g_xg0 + (size_t)k * G0 + g * H0 + j0);
                const uint4* wb = s_w + (size_t)w * 512;
                float a[4];
#pragma unroll
                for (int g = 0; g < 4; g++) {
                    const uint4* wg = wb + g * 128;
                    float s = 0.f;
#pragma unroll
                    for (int m = 0; m < 4; m++) {
                        uint4 wv = wg[m * 32 + lane];
                        float2 p;
                        p = unpack_bf2(wv.x); s += p.x * h4[m].x     + p.y * h4[m].y;
                        p = unpack_bf2(wv.y); s += p.x * h4[m].z     + p.y * h4[m].w;
                        p = unpack_bf2(wv.z); s += p.x * h4[m + 4].x + p.y * h4[m + 4].y;
                        p = unpack_bf2(wv.w); s += p.x * h4[m + 4].z + p.y * h4[m + 4].w;
                    }
                    a[g] = s;
                }
#pragma unroll
                for (int off = 16; off > 0; off >>= 1)
#pragma unroll
                    for (int g = 0; g < 4; g++)
                        a[g] += __shfl_xor_sync(0xffffffffu, a[g], off);
#pragma unroll
                for (int g = 0; g < 4; g++) a[g] += xg[g];
                float ii = sigf(a[0]), ff = sigf(a[1]), gg = tanhf(a[2]), oo = sigf(a[3]);
                c_state = ff * c_state + ii * gg;
                float hval = oo * tanhf(c_state);
                if (lane == 0) g_h0h[(size_t)(k + 1) * H0 + j0] = hval;
            }
        } else if (role == 1) {
            // -------- Layer 1: time t = k-1 --------
            if (act01 && k >= 1 && k <= SEQ) {
                const float4* h0p = (const float4*)(g_h0h + (size_t)k * H0);
                const float4* h1p = (const float4*)(g_h1h + (size_t)(k - 1) * H1);
                float4 hA[8], hB[4];
#pragma unroll
                for (int m = 0; m < 8; m++) hA[m] = __ldcg(h0p + m * 32 + lane);
#pragma unroll
                for (int m = 0; m < 4; m++) hB[m] = __ldcg(h1p + m * 32 + lane);
                const uint4* wb = s_w + (size_t)w * 768;
                float a[4];
#pragma unroll
                for (int g = 0; g < 4; g++) {
                    const uint4* wg = wb + g * 192;
                    float s = 0.f;
#pragma unroll
                    for (int m = 0; m < 4; m++) {
                        uint4 wv = wg[m * 32 + lane];
                        float2 p;
                        p = unpack_bf2(wv.x); s += p.x * hA[m].x     + p.y * hA[m].y;
                        p = unpack_bf2(wv.y); s += p.x * hA[m].z     + p.y * hA[m].w;
                        p = unpack_bf2(wv.z); s += p.x * hA[m + 4].x + p.y * hA[m + 4].y;
                        p = unpack_bf2(wv.w); s += p.x * hA[m + 4].z + p.y * hA[m + 4].w;
                    }
                    const uint4* wgh = wg + 128;
#pragma unroll
                    for (int m = 0; m < 2; m++) {
                        uint4 wv = wgh[m * 32 + lane];
                        float2 p;
                        p = unpack_bf2(wv.x); s += p.x * hB[m].x     + p.y * hB[m].y;
                        p = unpack_bf2(wv.y); s += p.x * hB[m].z     + p.y * hB[m].w;
                        p = unpack_bf2(wv.z); s += p.x * hB[m + 2].x + p.y * hB[m + 2].y;
                        p = unpack_bf2(wv.w); s += p.x * hB[m + 2].z + p.y * hB[m + 2].w;
                    }
                    a[g] = s;
                }
#pragma unroll
                for (int off = 16; off > 0; off >>= 1)
#pragma unroll
                    for (int g = 0; g < 4; g++)
                        a[g] += __shfl_xor_sync(0xffffffffu, a[g], off);
#pragma unroll
                for (int g = 0; g < 4; g++) a[g] += bsum[g];   // AFTER reduction
                float ii = sigf(a[0]), ff = sigf(a[1]), gg = tanhf(a[2]), oo = sigf(a[3]);
                c_state = ff * c_state + ii * gg;
                float hval = oo * tanhf(c_state);
                if (lane == 0) g_h1h[(size_t)k * H1 + j0] = hval;
            }
        } else {
            // -------- Layer 2: time t = k-2 (two elements per warp) --------
            if (k >= 2 && k <= SEQ + 1) {
                const float4* h1p = (const float4*)(g_h1h + (size_t)(k - 1) * H1);
                const float4* h2p = (const float4*)(g_h2h + (size_t)(k - 2) * H2);
                float4 hA[4], hB[2];
#pragma unroll
                for (int m = 0; m < 4; m++) hA[m] = __ldcg(h1p + m * 32 + lane);
#pragma unroll
                for (int m = 0; m < 2; m++) hB[m] = __ldcg(h2p + m * 32 + lane);
#pragma unroll
                for (int ee = 0; ee < 2; ee++) {
                    int e = w + ee * 16;
                    if (e < count) {
                        const uint4* wb = s_w + (size_t)e * 384;
                        float a[4];
#pragma unroll
                        for (int g = 0; g < 4; g++) {
                            const uint4* wg = wb + g * 96;
                            float s = 0.f;
#pragma unroll
                            for (int m = 0; m < 2; m++) {
                                uint4 wv = wg[m * 32 + lane];
                                float2 p;
                                p = unpack_bf2(wv.x); s += p.x * hA[m].x     + p.y * hA[m].y;
                                p = unpack_bf2(wv.y); s += p.x * hA[m].z     + p.y * hA[m].w;
                                p = unpack_bf2(wv.z); s += p.x * hA[m + 2].x + p.y * hA[m + 2].y;
                                p = unpack_bf2(wv.w); s += p.x * hA[m + 2].z + p.y * hA[m + 2].w;
                            }
                            {
                                uint4 wv = wg[64 + lane];
                                float2 p;
                                p = unpack_bf2(wv.x); s += p.x * hB[0].x + p.y * hB[0].y;
                                p = unpack_bf2(wv.y); s += p.x * hB[0].z + p.y * hB[0].w;
                                p = unpack_bf2(wv.z); s += p.x * hB[1].x + p.y * hB[1].y;
                                p = unpack_bf2(wv.w); s += p.x * hB[1].z + p.y * hB[1].w;
                            }
                            a[g] = s;
                        }
#pragma unroll
                        for (int off = 16; off > 0; off >>= 1)
#pragma unroll
                            for (int g = 0; g < 4; g++)
                                a[g] += __shfl_xor_sync(0xffffffffu, a[g], off);
#pragma unroll
                        for (int g = 0; g < 4; g++) a[g] += bb2[ee][g];   // AFTER reduction
                        float ii = sigf(a[0]), ff = sigf(a[1]), gg = tanhf(a[2]), oo = sigf(a[3]);
                        c2[ee] = ff * c2[ee] + ii * gg;
                        float hval = oo * tanhf(c2[ee]);
                        if (lane == 0) g_h2h[(size_t)(k - 1) * H2 + base + e] = hval;
                    }
                }
            }
        }
        grid.sync();   // single call site for the whole grid
    }
}

// ---------------------------------------------------------------------------
// Kernel 3: out[t][o] = h2(t) . Wlin[o] + blin[o]   (1024 x 7 x 256)
// ---------------------------------------------------------------------------
__global__ void linout_kernel(const float* __restrict__ Wlin,
                              const float* __restrict__ blin,
                              float* __restrict__ out) {
    const int w = threadIdx.x >> 5, lane = threadIdx.x & 31;
    const int t = blockIdx.x * 4 + w;
    float hv[8];
#pragma unroll
    for (int m = 0; m < 8; m++) hv[m] = g_h2h[(size_t)(t + 1) * H2 + m * 32 + lane];
#pragma unroll
    for (int o = 0; o < OUTD; o++) {
        float acc = 0.f;
#pragma unroll
        for (int m = 0; m < 8; m++)
            acc += hv[m] * __ldg(Wlin + o * H2 + m * 32 + lane);
#pragma unroll
        for (int off = 16; off > 0; off >>= 1)
            acc += __shfl_xor_sync(0xffffffffu, acc, off);
        if (lane == 0) out[t * OUTD + o] = acc + __ldg(blin + o);
    }
}

// ---------------------------------------------------------------------------
extern "C" void kernel_launch(void* const* d_in, const int* in_sizes, int n_in,
                              void* d_out, int out_size) {
    const int*   tokens = (const int*)d_in[0];
    const float* emb  = (const float*)d_in[1];
    const float* Wih0 = (const float*)d_in[2];
    const float* Whh0 = (const float*)d_in[3];
    const float* bih0 = (const float*)d_in[4];
    const float* bhh0 = (const float*)d_in[5];
    const float* Wih1 = (const float*)d_in[6];
    const float* Whh1 = (const float*)d_in[7];
    const float* bih1 = (const float*)d_in[8];
    const float* bhh1 = (const float*)d_in[9];
    const float* Wih2 = (const float*)d_in[10];
    const float* Whh2 = (const float*)d_in[11];
    const float* bih2 = (const float*)d_in[12];
    const float* bhh2 = (const float*)d_in[13];
    const float* Wlin = (const float*)d_in[14];
    const float* blin = (const float*)d_in[15];
    float* out = (float*)d_out;

    cudaFuncSetAttribute(recur_coop, cudaFuncAttributeMaxDynamicSharedMemorySize, SMEM_BYTES);

    xgemm_kernel<<<dim3(G0 / 64, SEQ / 64), 256>>>(tokens, emb, Wih0, bih0, bhh0);

    const float* a0 = Whh0;
    const float* a1 = Wih1; const float* a2 = Whh1;
    const float* a3 = bih1; const float* a4 = bhh1;
    const float* a5 = Wih2; const float* a6 = Whh2;
    const float* a7 = bih2; const float* a8 = bhh2;
    void* args[] = { (void*)&a0, (void*)&a1, (void*)&a2, (void*)&a3, (void*)&a4,
                     (void*)&a5, (void*)&a6, (void*)&a7, (void*)&a8 };
    cudaLaunchCooperativeKernel((void*)recur_coop,
                                dim3(NCTA), dim3(512), args, SMEM_BYTES, (cudaStream_t)0);

    linout_kernel<<<SEQ / 4, 128>>>(Wlin, blin, out);
}